// round 8
// baseline (speedup 1.0000x reference)
#include <cuda_runtime.h>
#include <cstdint>

// ---------------- problem constants ----------------
#define NN    1024
#define DD    384
#define KK    64
#define POSW  15
#define NBINS 64
#define NDEPTH 4
#define BSZ   256
#define NCB   6            // column blocks (384/64)
#define NPART (NCB * 4)    // pos-partial slots: col-block x warp N-quarter

// ---------------- persistent device scratch ----------------
__device__ float g_based[NN * BSZ];
__device__ float g_local[NN * DD];              // fp32 master
__device__ float g_locH[NN * DD];               // tf32 hi of local
__device__ float g_locL[NN * DD];               // tf32 lo of local
__device__ float g_msgH[NN * DD];
__device__ float g_msgL[NN * DD];
__device__ float g_WnH[DD * DD];
__device__ float g_WnL[DD * DD];
__device__ float g_pos[NN * POSW];
__device__ float g_pospart[NPART * NN * POSW];
__device__ float g_S[NN * BSZ];                 // 0/1 selection (exact tf32)

// ---------------- threefry2x32 (bit-exact JAX) ----------------
__host__ __device__ __forceinline__ uint32_t rotl32(uint32_t x, int r) {
    return (x << r) | (x >> (32 - r));
}

__host__ __device__ __forceinline__ void tf2x32(uint32_t k0, uint32_t k1,
                                                uint32_t x0, uint32_t x1,
                                                uint32_t& o0, uint32_t& o1) {
    uint32_t ks2 = k0 ^ k1 ^ 0x1BD11BDAu;
#define TFR(r) { x0 += x1; x1 = rotl32(x1, r); x1 ^= x0; }
    x0 += k0;  x1 += k1;
    TFR(13) TFR(15) TFR(26) TFR(6)
    x0 += k1;  x1 += ks2 + 1u;
    TFR(17) TFR(29) TFR(16) TFR(24)
    x0 += ks2; x1 += k0 + 2u;
    TFR(13) TFR(15) TFR(26) TFR(6)
    x0 += k0;  x1 += k1 + 3u;
    TFR(17) TFR(29) TFR(16) TFR(24)
    x0 += k1;  x1 += ks2 + 4u;
    TFR(13) TFR(15) TFR(26) TFR(6)
    x0 += ks2; x1 += k0 + 5u;
#undef TFR
    o0 = x0; o1 = x1;
}

__device__ __forceinline__ float gumbel_from_bits(uint32_t b) {
    float u = __uint_as_float(0x3F800000u | (b >> 9)) - 1.0f;
    return -logf(-logf(u + 1e-6f) + 1e-6f);
}

__device__ __forceinline__ uint32_t to_tf32(float x) {
    uint32_t r;
    asm("cvt.rna.tf32.f32 %0, %1;" : "=r"(r) : "f"(x));
    return r;
}
__device__ __forceinline__ float to_tf32f(float x) {
    return __uint_as_float(to_tf32(x));
}

__device__ __forceinline__ void mma_tf32(float* c, const uint32_t* a, const uint32_t* b) {
    asm volatile(
        "mma.sync.aligned.m16n8k8.row.col.f32.tf32.tf32.f32 "
        "{%0,%1,%2,%3},{%4,%5,%6,%7},{%8,%9},{%0,%1,%2,%3};"
        : "+f"(c[0]), "+f"(c[1]), "+f"(c[2]), "+f"(c[3])
        : "r"(a[0]), "r"(a[1]), "r"(a[2]), "r"(a[3]), "r"(b[0]), "r"(b[1]));
}

// ---------------- prep: Wn and initial local -> tf32 hi/lo -------------
__global__ void prep_kernel(const float* __restrict__ Wn,
                            const float* __restrict__ local) {
    int idx = blockIdx.x * 256 + threadIdx.x;
    if (idx < DD * DD) {
        float v = Wn[idx];
        float h = to_tf32f(v);
        g_WnH[idx] = h;
        g_WnL[idx] = to_tf32f(v - h);
    }
    if (idx < NN * DD) {
        float v = local[idx];
        float h = to_tf32f(v);
        g_locH[idx] = h;
        g_locL[idx] = to_tf32f(v - h);
    }
}

// ---------------- kernel: step-invariant base distance ----------------
__global__ void based_kernel(const float* __restrict__ prev_pos,
                             const float* __restrict__ disto,
                             const int* __restrict__ resi,
                             const int* __restrict__ chain,
                             const int* __restrict__ batch) {
    int gid = blockIdx.x * blockDim.x + threadIdx.x;
    if (gid >= NN * BSZ) return;
    int i  = gid >> 8;
    int jj = gid & 255;
    int b  = batch[i];
    int j  = b * BSZ + jj;

    const float4* dp = (const float4*)(disto + ((size_t)i * NN + j) * NBINS);
    float4 v[16];
    float mx = -1e30f;
#pragma unroll
    for (int q = 0; q < 16; q++) {
        v[q] = dp[q];
        mx = fmaxf(mx, fmaxf(fmaxf(v[q].x, v[q].y), fmaxf(v[q].z, v[q].w)));
    }
    const float step = 22.0f / 64.0f;
    float se = 0.0f, swc = 0.0f;
#pragma unroll
    for (int q = 0; q < 16; q++) {
        float e0 = expf(v[q].x - mx), e1 = expf(v[q].y - mx);
        float e2 = expf(v[q].z - mx), e3 = expf(v[q].w - mx);
        se  += e0 + e1 + e2 + e3;
        swc += e0 * (step * (4*q + 0) + 0.5f*step)
             + e1 * (step * (4*q + 1) + 0.5f*step)
             + e2 * (step * (4*q + 2) + 0.5f*step)
             + e3 * (step * (4*q + 3) + 0.5f*step);
    }
    float md = swc / se;

    float d = __int_as_float(0x7f800000);
    if (chain[i] == chain[j]) {
        d = fabsf((float)(resi[i] - resi[j])) * 3.81f;
    }
    if (md < 8.0f) d = fminf(d, md);

    float dx = prev_pos[i * POSW + 3] - prev_pos[j * POSW + 3];
    float dy = prev_pos[i * POSW + 4] - prev_pos[j * POSW + 4];
    float dz = prev_pos[i * POSW + 5] - prev_pos[j * POSW + 5];
    d = fminf(d, sqrtf(dx * dx + dy * dy + dz * dz));

    g_based[gid] = d;
}

// -------- top-K (hybrid shfl bitonic) -> selection matrix row ----------
__global__ void __launch_bounds__(256) topk_kernel(uint32_t k0, uint32_t k1,
                                                   const int* __restrict__ batch) {
    int i   = blockIdx.x;
    int tid = threadIdx.x;
    int b   = batch[i];

    __shared__ unsigned long long s[BSZ];
    __shared__ float srow[BSZ];

    unsigned long long K;
    {
        int jj = tid;
        int j  = b * BSZ + jj;
        float cx = g_pos[i * POSW + 3], cy = g_pos[i * POSW + 4], cz = g_pos[i * POSW + 5];
        float dx = cx - g_pos[j * POSW + 3];
        float dy = cy - g_pos[j * POSW + 4];
        float dz = cz - g_pos[j * POSW + 5];
        float d  = fminf(g_based[i * BSZ + jj], sqrtf(dx * dx + dy * dy + dz * dz));

        uint32_t o0, o1;
        tf2x32(k0, k1, 0u, (uint32_t)(i * NN + j), o0, o1);
        float g = gumbel_from_bits(o0 ^ o1);
        float rd = 3.0f * d - g;

        uint32_t ub = __float_as_uint(rd);
        ub = (ub & 0x80000000u) ? ~ub : (ub | 0x80000000u);
        K = ((unsigned long long)ub << 32) | (unsigned)jj;
    }

    srow[tid] = 0.0f;

    for (unsigned k = 2; k <= BSZ; k <<= 1) {
        bool up = ((tid & k) == 0);
        for (unsigned st = k >> 1; st > 0; st >>= 1) {
            unsigned long long other;
            if (st >= 32) {
                s[tid] = K;
                __syncthreads();
                other = s[tid ^ st];
                __syncthreads();
            } else {
                other = __shfl_xor_sync(0xFFFFFFFFu, K, st);
            }
            bool lower = ((tid & st) == 0);
            bool keepmin = (up == lower);
            K = keepmin ? (K < other ? K : other) : (K > other ? K : other);
        }
    }

    if (tid < KK)
        srow[(int)(K & 0xffffffffu)] = 1.0f;
    __syncthreads();

    g_S[i * BSZ + tid] = srow[tid];
}

#define GBK  32
#define AST  36
#define BSTN 72

// -------- msg GEMM: msg = (1/64) * S @ local; writes msg hi/lo ---------
// 32x64 tiles, grid (6, 32), 256 threads (8 warps, warp tile 16x16)
__global__ void __launch_bounds__(256) msg_gemm_tc() {
    __shared__ float As[2][GBK * AST];          // S tile [m][k]
    __shared__ float BsH[2][GBK * BSTN];        // local hi [k][n]
    __shared__ float BsL[2][GBK * BSTN];        // local lo [k][n]

    int tid  = threadIdx.x;
    int warp = tid >> 5, lane = tid & 31;
    int wm = (warp & 1) * 16;
    int wn = (warp >> 1) * 16;
    int row0 = blockIdx.y * 32;
    int col0 = blockIdx.x * 64;
    int bsrc = (row0 >> 8) * BSZ;
    int g  = lane >> 2;
    int tg = lane & 3;

    float acc[2][4] = {};

    int am = tid >> 3;            // 0..31
    int ak = (tid & 7) * 4;       // 0..28
    int bk = tid >> 3;            // 0..31
    int bn = (tid & 7) * 8;       // 0..56

    uint32_t sa[2], sbh[2], sbl[2];
    sa[0]  = (uint32_t)__cvta_generic_to_shared(&As[0][am * AST + ak]);
    sa[1]  = (uint32_t)__cvta_generic_to_shared(&As[1][am * AST + ak]);
    sbh[0] = (uint32_t)__cvta_generic_to_shared(&BsH[0][bk * BSTN + bn]);
    sbh[1] = (uint32_t)__cvta_generic_to_shared(&BsH[1][bk * BSTN + bn]);
    sbl[0] = (uint32_t)__cvta_generic_to_shared(&BsL[0][bk * BSTN + bn]);
    sbl[1] = (uint32_t)__cvta_generic_to_shared(&BsL[1][bk * BSTN + bn]);

#define MSTAGE(it, buf)                                                          \
    {                                                                            \
        int k0 = (it) * GBK;                                                     \
        const float* gp = &g_S[(row0 + am) * BSZ + k0 + ak];                     \
        asm volatile("cp.async.cg.shared.global [%0],[%1],16;" :: "r"(sa[buf]), "l"(gp)); \
        const float* gh = &g_locH[(size_t)(bsrc + k0 + bk) * DD + col0 + bn];    \
        asm volatile("cp.async.cg.shared.global [%0],[%1],16;" :: "r"(sbh[buf]), "l"(gh)); \
        asm volatile("cp.async.cg.shared.global [%0],[%1],16;" :: "r"(sbh[buf] + 16), "l"(gh + 4)); \
        const float* gl = &g_locL[(size_t)(bsrc + k0 + bk) * DD + col0 + bn];    \
        asm volatile("cp.async.cg.shared.global [%0],[%1],16;" :: "r"(sbl[buf]), "l"(gl)); \
        asm volatile("cp.async.cg.shared.global [%0],[%1],16;" :: "r"(sbl[buf] + 16), "l"(gl + 4)); \
        asm volatile("cp.async.commit_group;");                                  \
    }

    MSTAGE(0, 0)

    const int NKM = BSZ / GBK;    // 8
    for (int it = 0; it < NKM; ++it) {
        int cur = it & 1;
        if (it + 1 < NKM) {
            MSTAGE(it + 1, !cur)
            asm volatile("cp.async.wait_group 1;");
        } else {
            asm volatile("cp.async.wait_group 0;");
        }
        __syncthreads();

        const float* A  = As[cur];
        const float* BH = BsH[cur];
        const float* BL = BsL[cur];
#pragma unroll
        for (int ks = 0; ks < GBK; ks += 8) {
            // S is 0/1: raw fp32 bits are valid tf32, no cvt
            uint32_t ah[4] = {
                __float_as_uint(A[(wm + g) * AST + ks + tg]),
                __float_as_uint(A[(wm + g + 8) * AST + ks + tg]),
                __float_as_uint(A[(wm + g) * AST + ks + tg + 4]),
                __float_as_uint(A[(wm + g + 8) * AST + ks + tg + 4]) };
#pragma unroll
            for (int nj = 0; nj < 2; nj++) {
                int cc = wn + nj * 8 + g;
                uint32_t bh[2] = { __float_as_uint(BH[(ks + tg) * BSTN + cc]),
                                   __float_as_uint(BH[(ks + tg + 4) * BSTN + cc]) };
                uint32_t bl[2] = { __float_as_uint(BL[(ks + tg) * BSTN + cc]),
                                   __float_as_uint(BL[(ks + tg + 4) * BSTN + cc]) };
                mma_tf32(acc[nj], ah, bl);
                mma_tf32(acc[nj], ah, bh);
            }
        }
        __syncthreads();
    }

    int r = row0 + wm + g;
#pragma unroll
    for (int nj = 0; nj < 2; nj++) {
        int c = col0 + wn + nj * 8 + 2 * tg;
#pragma unroll
        for (int q = 0; q < 4; q++) {
            int rr = (q < 2) ? r : r + 8;
            int ccc = c + (q & 1);
            float v = acc[nj][q] * 0.015625f;
            float h = to_tf32f(v);
            g_msgH[rr * DD + ccc] = h;
            g_msgL[rr * DD + ccc] = to_tf32f(v - h);
        }
    }
}

// -------- main GEMM: local += gelu(msg @ Wn), fused pos partials -------
__device__ __forceinline__ float gelu_tanh(float x) {
    float x3 = x * x * x;
    float t = tanhf(0.7978845608028654f * (x + 0.044715f * x3));
    return 0.5f * x * (1.0f + t);
}

#define NKIT (DD / GBK)   // 12

__global__ void __launch_bounds__(256) gemm_gelu_tc(const float* __restrict__ Wp) {
    __shared__ float AsH[2][GBK * AST];
    __shared__ float AsL[2][GBK * AST];
    __shared__ float BsH[2][GBK * BSTN];
    __shared__ float BsL[2][GBK * BSTN];
    __shared__ float WpS[64 * POSW];

    int tid  = threadIdx.x;
    int warp = tid >> 5, lane = tid & 31;
    int wm = (warp & 1) * 16;
    int wn = (warp >> 1) * 16;
    int row0 = blockIdx.y * 32;
    int col0 = blockIdx.x * 64;
    int g  = lane >> 2;
    int tg = lane & 3;

    float acc[2][4] = {};

    int am = tid >> 3;
    int ak = (tid & 7) * 4;
    int bk = tid >> 3;
    int bn = (tid & 7) * 8;

    uint32_t sah[2], sal[2], sbh[2], sbl[2];
    sah[0] = (uint32_t)__cvta_generic_to_shared(&AsH[0][am * AST + ak]);
    sah[1] = (uint32_t)__cvta_generic_to_shared(&AsH[1][am * AST + ak]);
    sal[0] = (uint32_t)__cvta_generic_to_shared(&AsL[0][am * AST + ak]);
    sal[1] = (uint32_t)__cvta_generic_to_shared(&AsL[1][am * AST + ak]);
    sbh[0] = (uint32_t)__cvta_generic_to_shared(&BsH[0][bk * BSTN + bn]);
    sbh[1] = (uint32_t)__cvta_generic_to_shared(&BsH[1][bk * BSTN + bn]);
    sbl[0] = (uint32_t)__cvta_generic_to_shared(&BsL[0][bk * BSTN + bn]);
    sbl[1] = (uint32_t)__cvta_generic_to_shared(&BsL[1][bk * BSTN + bn]);

#define GSTAGE(it, buf)                                                          \
    {                                                                            \
        int k0 = (it) * GBK;                                                     \
        const float* gah = &g_msgH[(row0 + am) * DD + k0 + ak];                  \
        asm volatile("cp.async.cg.shared.global [%0],[%1],16;" :: "r"(sah[buf]), "l"(gah)); \
        const float* gal = &g_msgL[(row0 + am) * DD + k0 + ak];                  \
        asm volatile("cp.async.cg.shared.global [%0],[%1],16;" :: "r"(sal[buf]), "l"(gal)); \
        const float* gh = &g_WnH[(size_t)(k0 + bk) * DD + col0 + bn];            \
        asm volatile("cp.async.cg.shared.global [%0],[%1],16;" :: "r"(sbh[buf]), "l"(gh)); \
        asm volatile("cp.async.cg.shared.global [%0],[%1],16;" :: "r"(sbh[buf] + 16), "l"(gh + 4)); \
        const float* gl = &g_WnL[(size_t)(k0 + bk) * DD + col0 + bn];            \
        asm volatile("cp.async.cg.shared.global [%0],[%1],16;" :: "r"(sbl[buf]), "l"(gl)); \
        asm volatile("cp.async.cg.shared.global [%0],[%1],16;" :: "r"(sbl[buf] + 16), "l"(gl + 4)); \
        asm volatile("cp.async.commit_group;");                                  \
    }

    GSTAGE(0, 0)

    for (int idx = tid; idx < 64 * POSW; idx += 256)
        WpS[idx] = Wp[col0 * POSW + idx];

    for (int it = 0; it < NKIT; ++it) {
        int cur = it & 1;
        if (it + 1 < NKIT) {
            GSTAGE(it + 1, !cur)
            asm volatile("cp.async.wait_group 1;");
        } else {
            asm volatile("cp.async.wait_group 0;");
        }
        __syncthreads();

        const float* AH = AsH[cur];
        const float* AL = AsL[cur];
        const float* BH = BsH[cur];
        const float* BL = BsL[cur];
#pragma unroll
        for (int ks = 0; ks < GBK; ks += 8) {
            uint32_t ah[4] = {
                __float_as_uint(AH[(wm + g) * AST + ks + tg]),
                __float_as_uint(AH[(wm + g + 8) * AST + ks + tg]),
                __float_as_uint(AH[(wm + g) * AST + ks + tg + 4]),
                __float_as_uint(AH[(wm + g + 8) * AST + ks + tg + 4]) };
            uint32_t al[4] = {
                __float_as_uint(AL[(wm + g) * AST + ks + tg]),
                __float_as_uint(AL[(wm + g + 8) * AST + ks + tg]),
                __float_as_uint(AL[(wm + g) * AST + ks + tg + 4]),
                __float_as_uint(AL[(wm + g + 8) * AST + ks + tg + 4]) };
#pragma unroll
            for (int nj = 0; nj < 2; nj++) {
                int cc = wn + nj * 8 + g;
                uint32_t bh[2] = { __float_as_uint(BH[(ks + tg) * BSTN + cc]),
                                   __float_as_uint(BH[(ks + tg + 4) * BSTN + cc]) };
                uint32_t bl[2] = { __float_as_uint(BL[(ks + tg) * BSTN + cc]),
                                   __float_as_uint(BL[(ks + tg + 4) * BSTN + cc]) };
                mma_tf32(acc[nj], al, bh);
                mma_tf32(acc[nj], ah, bl);
                mma_tf32(acc[nj], ah, bh);
            }
        }
        __syncthreads();
    }

    // epilogue: local += gelu(acc); maintain hi/lo; pos partials
    int r = row0 + wm + g;
    float pp0[POSW], pp1[POSW];
#pragma unroll
    for (int o = 0; o < POSW; o++) { pp0[o] = 0.0f; pp1[o] = 0.0f; }

#pragma unroll
    for (int nj = 0; nj < 2; nj++) {
        int cl = wn + nj * 8 + 2 * tg;
        int c  = col0 + cl;
        float v00 = g_local[r * DD + c]           + gelu_tanh(acc[nj][0]);
        float v01 = g_local[r * DD + c + 1]       + gelu_tanh(acc[nj][1]);
        float v10 = g_local[(r + 8) * DD + c]     + gelu_tanh(acc[nj][2]);
        float v11 = g_local[(r + 8) * DD + c + 1] + gelu_tanh(acc[nj][3]);
        g_local[r * DD + c]           = v00;
        g_local[r * DD + c + 1]       = v01;
        g_local[(r + 8) * DD + c]     = v10;
        g_local[(r + 8) * DD + c + 1] = v11;
        float h;
        h = to_tf32f(v00); g_locH[r * DD + c]           = h; g_locL[r * DD + c]           = to_tf32f(v00 - h);
        h = to_tf32f(v01); g_locH[r * DD + c + 1]       = h; g_locL[r * DD + c + 1]       = to_tf32f(v01 - h);
        h = to_tf32f(v10); g_locH[(r + 8) * DD + c]     = h; g_locL[(r + 8) * DD + c]     = to_tf32f(v10 - h);
        h = to_tf32f(v11); g_locH[(r + 8) * DD + c + 1] = h; g_locL[(r + 8) * DD + c + 1] = to_tf32f(v11 - h);
#pragma unroll
        for (int o = 0; o < POSW; o++) {
            float w0 = WpS[cl * POSW + o];
            float w1 = WpS[(cl + 1) * POSW + o];
            pp0[o] += v00 * w0 + v01 * w1;
            pp1[o] += v10 * w0 + v11 * w1;
        }
    }

#pragma unroll
    for (int dlt = 1; dlt <= 2; dlt <<= 1)
#pragma unroll
        for (int o = 0; o < POSW; o++) {
            pp0[o] += __shfl_xor_sync(0xFFFFFFFFu, pp0[o], dlt);
            pp1[o] += __shfl_xor_sync(0xFFFFFFFFu, pp1[o], dlt);
        }

    if (tg == 0) {
        int slot = blockIdx.x * 4 + (wn >> 4);
        float* pb = &g_pospart[(size_t)slot * (NN * POSW)];
#pragma unroll
        for (int o = 0; o < POSW; o++) {
            pb[r * POSW + o]       = pp0[o];
            pb[(r + 8) * POSW + o] = pp1[o];
        }
    }
}

// ---------------- kernel: finalize pos + trajectory write --------------
__global__ void __launch_bounds__(128) finalize_pos(float* __restrict__ traj_out) {
    int gidx = blockIdx.x * 128 + threadIdx.x;             // 120 x 128 = 15360
    float acc = 0.0f;
#pragma unroll
    for (int cb = 0; cb < NPART; cb++)
        acc += g_pospart[(size_t)cb * (NN * POSW) + gidx];
    float p = g_pos[gidx] + 0.1f * acc;
    g_pos[gidx] = p;
    traj_out[gidx] = p;
}

// ---------------- launch ----------------
extern "C" void kernel_launch(void* const* d_in, const int* in_sizes, int n_in,
                              void* d_out, int out_size) {
    const float* local    = (const float*)d_in[0];
    const float* pos      = (const float*)d_in[1];
    const float* prev_pos = (const float*)d_in[2];
    const float* disto    = (const float*)d_in[3];
    const float* Wn       = (const float*)d_in[4];
    const float* Wp       = (const float*)d_in[5];
    const int*   resi     = (const int*)d_in[6];
    const int*   chain    = (const int*)d_in[7];
    const int*   batch    = (const int*)d_in[8];
    float* out = (float*)d_out;

    cudaMemcpyToSymbolAsync(g_local, local, (size_t)NN * DD * sizeof(float), 0,
                            cudaMemcpyDeviceToDevice, 0);
    cudaMemcpyToSymbolAsync(g_pos, pos, (size_t)NN * POSW * sizeof(float), 0,
                            cudaMemcpyDeviceToDevice, 0);

    prep_kernel<<<NN * DD / 256, 256>>>(Wn, local);
    based_kernel<<<NN * BSZ / 256, 256>>>(prev_pos, disto, resi, chain, batch);

    uint32_t fk0[NDEPTH], fk1[NDEPTH];
    for (int t = 0; t < NDEPTH; t++)
        tf2x32(0u, 42u, 0u, (uint32_t)t, fk0[t], fk1[t]);

    float* traj_base = out + (size_t)NN * DD + (size_t)NN * POSW;
    dim3 ggrid(DD / 64, NN / 32);

    for (int t = 0; t < NDEPTH; t++) {
        topk_kernel<<<NN, BSZ>>>(fk0[t], fk1[t], batch);
        msg_gemm_tc<<<ggrid, 256>>>();
        gemm_gelu_tc<<<ggrid, 256>>>(Wp);
        finalize_pos<<<NN * POSW / 128, 128>>>(traj_base + (size_t)t * NN * POSW);
    }

    cudaMemcpyFromSymbolAsync(out, g_local, (size_t)NN * DD * sizeof(float), 0,
                              cudaMemcpyDeviceToDevice, 0);
    cudaMemcpyFromSymbolAsync(out + (size_t)NN * DD, g_pos,
                              (size_t)NN * POSW * sizeof(float), 0,
                              cudaMemcpyDeviceToDevice, 0);
}

// round 9
// speedup vs baseline: 1.1339x; 1.1339x over previous
#include <cuda_runtime.h>
#include <cstdint>

// ---------------- problem constants ----------------
#define NN    1024
#define DD    384
#define KK    64
#define POSW  15
#define NBINS 64
#define NDEPTH 4
#define BSZ   256
#define NCB   6            // column blocks (384/64)
#define NPART (NCB * 2)    // pos-partial slots: col-block x warp N-half

// ---------------- persistent device scratch ----------------
__device__ float g_based[NN * BSZ];
__device__ float g_local[NN * DD];              // fp32 master (only copy)
__device__ float g_msgH[NN * DD];               // tf32 hi of msg
__device__ float g_msgL[NN * DD];               // tf32 lo of msg
__device__ float g_WnH[DD * DD];
__device__ float g_WnL[DD * DD];
__device__ float g_pos[NN * POSW];
__device__ float g_pospart[NPART * NN * POSW];
__device__ float g_S[NN * BSZ];                 // 0/1 selection (exact tf32)

// ---------------- threefry2x32 (bit-exact JAX) ----------------
__host__ __device__ __forceinline__ uint32_t rotl32(uint32_t x, int r) {
    return (x << r) | (x >> (32 - r));
}

__host__ __device__ __forceinline__ void tf2x32(uint32_t k0, uint32_t k1,
                                                uint32_t x0, uint32_t x1,
                                                uint32_t& o0, uint32_t& o1) {
    uint32_t ks2 = k0 ^ k1 ^ 0x1BD11BDAu;
#define TFR(r) { x0 += x1; x1 = rotl32(x1, r); x1 ^= x0; }
    x0 += k0;  x1 += k1;
    TFR(13) TFR(15) TFR(26) TFR(6)
    x0 += k1;  x1 += ks2 + 1u;
    TFR(17) TFR(29) TFR(16) TFR(24)
    x0 += ks2; x1 += k0 + 2u;
    TFR(13) TFR(15) TFR(26) TFR(6)
    x0 += k0;  x1 += k1 + 3u;
    TFR(17) TFR(29) TFR(16) TFR(24)
    x0 += k1;  x1 += ks2 + 4u;
    TFR(13) TFR(15) TFR(26) TFR(6)
    x0 += ks2; x1 += k0 + 5u;
#undef TFR
    o0 = x0; o1 = x1;
}

__device__ __forceinline__ float gumbel_from_bits(uint32_t b) {
    float u = __uint_as_float(0x3F800000u | (b >> 9)) - 1.0f;
    return -logf(-logf(u + 1e-6f) + 1e-6f);
}

__device__ __forceinline__ uint32_t to_tf32(float x) {
    uint32_t r;
    asm("cvt.rna.tf32.f32 %0, %1;" : "=r"(r) : "f"(x));
    return r;
}
__device__ __forceinline__ float to_tf32f(float x) {
    return __uint_as_float(to_tf32(x));
}

__device__ __forceinline__ void mma_tf32(float* c, const uint32_t* a, const uint32_t* b) {
    asm volatile(
        "mma.sync.aligned.m16n8k8.row.col.f32.tf32.tf32.f32 "
        "{%0,%1,%2,%3},{%4,%5,%6,%7},{%8,%9},{%0,%1,%2,%3};"
        : "+f"(c[0]), "+f"(c[1]), "+f"(c[2]), "+f"(c[3])
        : "r"(a[0]), "r"(a[1]), "r"(a[2]), "r"(a[3]), "r"(b[0]), "r"(b[1]));
}

// ---------------- prep: Wn -> tf32 hi/lo (once) -------------------------
__global__ void prep_kernel(const float* __restrict__ Wn) {
    int idx = blockIdx.x * 256 + threadIdx.x;
    if (idx < DD * DD) {
        float v = Wn[idx];
        float h = to_tf32f(v);
        g_WnH[idx] = h;
        g_WnL[idx] = to_tf32f(v - h);
    }
}

// ---------------- kernel: step-invariant base distance ----------------
__global__ void based_kernel(const float* __restrict__ prev_pos,
                             const float* __restrict__ disto,
                             const int* __restrict__ resi,
                             const int* __restrict__ chain,
                             const int* __restrict__ batch) {
    int gid = blockIdx.x * blockDim.x + threadIdx.x;
    if (gid >= NN * BSZ) return;
    int i  = gid >> 8;
    int jj = gid & 255;
    int b  = batch[i];
    int j  = b * BSZ + jj;

    const float4* dp = (const float4*)(disto + ((size_t)i * NN + j) * NBINS);
    float4 v[16];
    float mx = -1e30f;
#pragma unroll
    for (int q = 0; q < 16; q++) {
        v[q] = dp[q];
        mx = fmaxf(mx, fmaxf(fmaxf(v[q].x, v[q].y), fmaxf(v[q].z, v[q].w)));
    }
    const float step = 22.0f / 64.0f;
    float se = 0.0f, swc = 0.0f;
#pragma unroll
    for (int q = 0; q < 16; q++) {
        float e0 = expf(v[q].x - mx), e1 = expf(v[q].y - mx);
        float e2 = expf(v[q].z - mx), e3 = expf(v[q].w - mx);
        se  += e0 + e1 + e2 + e3;
        swc += e0 * (step * (4*q + 0) + 0.5f*step)
             + e1 * (step * (4*q + 1) + 0.5f*step)
             + e2 * (step * (4*q + 2) + 0.5f*step)
             + e3 * (step * (4*q + 3) + 0.5f*step);
    }
    float md = swc / se;

    float d = __int_as_float(0x7f800000);
    if (chain[i] == chain[j]) {
        d = fabsf((float)(resi[i] - resi[j])) * 3.81f;
    }
    if (md < 8.0f) d = fminf(d, md);

    float dx = prev_pos[i * POSW + 3] - prev_pos[j * POSW + 3];
    float dy = prev_pos[i * POSW + 4] - prev_pos[j * POSW + 4];
    float dz = prev_pos[i * POSW + 5] - prev_pos[j * POSW + 5];
    d = fminf(d, sqrtf(dx * dx + dy * dy + dz * dz));

    g_based[gid] = d;
}

// -------- top-K (hybrid shfl bitonic) -> selection matrix row ----------
__global__ void __launch_bounds__(256) topk_kernel(uint32_t k0, uint32_t k1,
                                                   const int* __restrict__ batch) {
    int i   = blockIdx.x;
    int tid = threadIdx.x;
    int b   = batch[i];

    __shared__ unsigned long long s[BSZ];
    __shared__ float srow[BSZ];

    unsigned long long K;
    {
        int jj = tid;
        int j  = b * BSZ + jj;
        float cx = g_pos[i * POSW + 3], cy = g_pos[i * POSW + 4], cz = g_pos[i * POSW + 5];
        float dx = cx - g_pos[j * POSW + 3];
        float dy = cy - g_pos[j * POSW + 4];
        float dz = cz - g_pos[j * POSW + 5];
        float d  = fminf(g_based[i * BSZ + jj], sqrtf(dx * dx + dy * dy + dz * dz));

        uint32_t o0, o1;
        tf2x32(k0, k1, 0u, (uint32_t)(i * NN + j), o0, o1);
        float g = gumbel_from_bits(o0 ^ o1);
        float rd = 3.0f * d - g;

        uint32_t ub = __float_as_uint(rd);
        ub = (ub & 0x80000000u) ? ~ub : (ub | 0x80000000u);
        K = ((unsigned long long)ub << 32) | (unsigned)jj;
    }

    srow[tid] = 0.0f;

    for (unsigned k = 2; k <= BSZ; k <<= 1) {
        bool up = ((tid & k) == 0);
        for (unsigned st = k >> 1; st > 0; st >>= 1) {
            unsigned long long other;
            if (st >= 32) {
                s[tid] = K;
                __syncthreads();
                other = s[tid ^ st];
                __syncthreads();
            } else {
                other = __shfl_xor_sync(0xFFFFFFFFu, K, st);
            }
            bool lower = ((tid & st) == 0);
            bool keepmin = (up == lower);
            K = keepmin ? (K < other ? K : other) : (K > other ? K : other);
        }
    }

    if (tid < KK)
        srow[(int)(K & 0xffffffffu)] = 1.0f;
    __syncthreads();

    g_S[i * BSZ + tid] = srow[tid];
}

#define GBK  32
#define AST  36
#define BSTN 72

// -------- msg GEMM: msg = (1/64) * S @ local; emits msg hi/lo ----------
// 64x64 tiles, grid (6, 16), 256 threads, warp tile 16x32 (R7 layout)
__global__ void __launch_bounds__(256) msg_gemm_tc() {
    __shared__ float As[2][64 * AST];
    __shared__ float Bs[2][GBK * BSTN];

    int tid  = threadIdx.x;
    int warp = tid >> 5, lane = tid & 31;
    int wm = (warp & 3) * 16;
    int wn = (warp >> 2) * 32;
    int row0 = blockIdx.y * 64;
    int col0 = blockIdx.x * 64;
    int bsrc = (row0 >> 8) * BSZ;
    int g  = lane >> 2;
    int tg = lane & 3;

    float acc[4][4] = {};

    int am = tid >> 2;
    int ak = (tid & 3) * 8;
    int bk = tid >> 3;
    int bn = (tid & 7) * 8;

    uint32_t sa0 = (uint32_t)__cvta_generic_to_shared(&As[0][am * AST + ak]);
    uint32_t sa1 = (uint32_t)__cvta_generic_to_shared(&As[1][am * AST + ak]);
    uint32_t sb0 = (uint32_t)__cvta_generic_to_shared(&Bs[0][bk * BSTN + bn]);
    uint32_t sb1 = (uint32_t)__cvta_generic_to_shared(&Bs[1][bk * BSTN + bn]);

#define MSTAGE(it, SA, SB)                                                       \
    {                                                                            \
        int k0 = (it) * GBK;                                                     \
        const float* gp = &g_S[(row0 + am) * BSZ + k0 + ak];                     \
        asm volatile("cp.async.cg.shared.global [%0],[%1],16;" :: "r"(SA), "l"(gp)); \
        asm volatile("cp.async.cg.shared.global [%0],[%1],16;" :: "r"(SA + 16), "l"(gp + 4)); \
        const float* gq = &g_local[(size_t)(bsrc + k0 + bk) * DD + col0 + bn];   \
        asm volatile("cp.async.cg.shared.global [%0],[%1],16;" :: "r"(SB), "l"(gq)); \
        asm volatile("cp.async.cg.shared.global [%0],[%1],16;" :: "r"(SB + 16), "l"(gq + 4)); \
        asm volatile("cp.async.commit_group;");                                  \
    }

    MSTAGE(0, sa0, sb0)

    const int NKM = BSZ / GBK;    // 8
    for (int it = 0; it < NKM; ++it) {
        int cur = it & 1;
        if (it + 1 < NKM) {
            if (cur) MSTAGE(it + 1, sa0, sb0)
            else     MSTAGE(it + 1, sa1, sb1)
            asm volatile("cp.async.wait_group 1;");
        } else {
            asm volatile("cp.async.wait_group 0;");
        }
        __syncthreads();

        const float* A = As[cur];
        const float* B = Bs[cur];
#pragma unroll
        for (int ks = 0; ks < GBK; ks += 8) {
            // S is 0/1: raw fp32 bits are exact tf32, no cvt
            uint32_t ah[4] = {
                __float_as_uint(A[(wm + g) * AST + ks + tg]),
                __float_as_uint(A[(wm + g + 8) * AST + ks + tg]),
                __float_as_uint(A[(wm + g) * AST + ks + tg + 4]),
                __float_as_uint(A[(wm + g + 8) * AST + ks + tg + 4]) };
#pragma unroll
            for (int nj = 0; nj < 4; nj++) {
                float b0 = B[(ks + tg) * BSTN + wn + nj * 8 + g];
                float b1 = B[(ks + tg + 4) * BSTN + wn + nj * 8 + g];
                uint32_t bh[2] = { to_tf32(b0), to_tf32(b1) };
                uint32_t bl[2] = { to_tf32(b0 - __uint_as_float(bh[0])),
                                   to_tf32(b1 - __uint_as_float(bh[1])) };
                mma_tf32(acc[nj], ah, bl);
                mma_tf32(acc[nj], ah, bh);
            }
        }
        __syncthreads();
    }

    int r = row0 + wm + g;
#pragma unroll
    for (int nj = 0; nj < 4; nj++) {
        int c = col0 + wn + nj * 8 + 2 * tg;
#pragma unroll
        for (int q = 0; q < 4; q++) {
            int rr  = (q < 2) ? r : r + 8;
            int ccc = c + (q & 1);
            float v = acc[nj][q] * 0.015625f;
            float h = to_tf32f(v);
            g_msgH[rr * DD + ccc] = h;
            g_msgL[rr * DD + ccc] = to_tf32f(v - h);
        }
    }
}

// -------- main GEMM: local += gelu(msg @ Wn), zero-cvt inner loop ------
__device__ __forceinline__ float gelu_tanh(float x) {
    float x3 = x * x * x;
    float t = tanhf(0.7978845608028654f * (x + 0.044715f * x3));
    return 0.5f * x * (1.0f + t);
}

#define GK    16
#define ASTG  20   // A[m][k] stride (k=16): 20 ≡ 4 mod 32 -> conflict-free quads
#define NKIT2 (DD / GK)   // 24

__global__ void __launch_bounds__(256) gemm_gelu_tc(const float* __restrict__ Wp) {
    __shared__ float AsH[2][64 * ASTG];     // 10.24 KB
    __shared__ float AsL[2][64 * ASTG];     // 10.24 KB
    __shared__ float BsH[2][GK * BSTN];     //  9.22 KB
    __shared__ float BsL[2][GK * BSTN];     //  9.22 KB
    __shared__ float WpS[64 * POSW];        //  3.84 KB  (total ~42.8 KB)

    int tid  = threadIdx.x;
    int warp = tid >> 5, lane = tid & 31;
    int wm = (warp & 3) * 16;
    int wn = (warp >> 2) * 32;
    int row0 = blockIdx.y * 64;
    int col0 = blockIdx.x * 64;
    int g  = lane >> 2;
    int tg = lane & 3;

    float acc[4][4] = {};

    int am = tid >> 2;            // 0..63
    int ak = (tid & 3) * 4;       // 0,4,8,12
    int bk = tid >> 4;            // 0..15
    int bn = (tid & 15) * 4;      // 0..60

    uint32_t sah[2], sal[2], sbh[2], sbl[2];
    sah[0] = (uint32_t)__cvta_generic_to_shared(&AsH[0][am * ASTG + ak]);
    sah[1] = (uint32_t)__cvta_generic_to_shared(&AsH[1][am * ASTG + ak]);
    sal[0] = (uint32_t)__cvta_generic_to_shared(&AsL[0][am * ASTG + ak]);
    sal[1] = (uint32_t)__cvta_generic_to_shared(&AsL[1][am * ASTG + ak]);
    sbh[0] = (uint32_t)__cvta_generic_to_shared(&BsH[0][bk * BSTN + bn]);
    sbh[1] = (uint32_t)__cvta_generic_to_shared(&BsH[1][bk * BSTN + bn]);
    sbl[0] = (uint32_t)__cvta_generic_to_shared(&BsL[0][bk * BSTN + bn]);
    sbl[1] = (uint32_t)__cvta_generic_to_shared(&BsL[1][bk * BSTN + bn]);

#define GSTAGE(it, buf)                                                          \
    {                                                                            \
        int k0 = (it) * GK;                                                      \
        const float* pah = &g_msgH[(row0 + am) * DD + k0 + ak];                  \
        asm volatile("cp.async.cg.shared.global [%0],[%1],16;" :: "r"(sah[buf]), "l"(pah)); \
        const float* pal = &g_msgL[(row0 + am) * DD + k0 + ak];                  \
        asm volatile("cp.async.cg.shared.global [%0],[%1],16;" :: "r"(sal[buf]), "l"(pal)); \
        const float* pbh = &g_WnH[(size_t)(k0 + bk) * DD + col0 + bn];           \
        asm volatile("cp.async.cg.shared.global [%0],[%1],16;" :: "r"(sbh[buf]), "l"(pbh)); \
        const float* pbl = &g_WnL[(size_t)(k0 + bk) * DD + col0 + bn];           \
        asm volatile("cp.async.cg.shared.global [%0],[%1],16;" :: "r"(sbl[buf]), "l"(pbl)); \
        asm volatile("cp.async.commit_group;");                                  \
    }

    GSTAGE(0, 0)

    for (int idx = tid; idx < 64 * POSW; idx += 256)
        WpS[idx] = Wp[col0 * POSW + idx];

    for (int it = 0; it < NKIT2; ++it) {
        int cur = it & 1;
        if (it + 1 < NKIT2) {
            GSTAGE(it + 1, !cur)
            asm volatile("cp.async.wait_group 1;");
        } else {
            asm volatile("cp.async.wait_group 0;");
        }
        __syncthreads();

        const float* AH = AsH[cur];
        const float* AL = AsL[cur];
        const float* BH = BsH[cur];
        const float* BL = BsL[cur];
#pragma unroll
        for (int ks = 0; ks < GK; ks += 8) {
            uint32_t ah[4] = {
                __float_as_uint(AH[(wm + g) * ASTG + ks + tg]),
                __float_as_uint(AH[(wm + g + 8) * ASTG + ks + tg]),
                __float_as_uint(AH[(wm + g) * ASTG + ks + tg + 4]),
                __float_as_uint(AH[(wm + g + 8) * ASTG + ks + tg + 4]) };
            uint32_t al[4] = {
                __float_as_uint(AL[(wm + g) * ASTG + ks + tg]),
                __float_as_uint(AL[(wm + g + 8) * ASTG + ks + tg]),
                __float_as_uint(AL[(wm + g) * ASTG + ks + tg + 4]),
                __float_as_uint(AL[(wm + g + 8) * ASTG + ks + tg + 4]) };
#pragma unroll
            for (int nj = 0; nj < 4; nj++) {
                int cc = wn + nj * 8 + g;
                uint32_t bh[2] = { __float_as_uint(BH[(ks + tg) * BSTN + cc]),
                                   __float_as_uint(BH[(ks + tg + 4) * BSTN + cc]) };
                uint32_t bl[2] = { __float_as_uint(BL[(ks + tg) * BSTN + cc]),
                                   __float_as_uint(BL[(ks + tg + 4) * BSTN + cc]) };
                mma_tf32(acc[nj], al, bh);
                mma_tf32(acc[nj], ah, bl);
                mma_tf32(acc[nj], ah, bh);
            }
        }
        __syncthreads();
    }

    // epilogue: local += gelu(acc); pos partials (R7 scheme)
    int r = row0 + wm + g;
    float pp0[POSW], pp1[POSW];
#pragma unroll
    for (int o = 0; o < POSW; o++) { pp0[o] = 0.0f; pp1[o] = 0.0f; }

#pragma unroll
    for (int nj = 0; nj < 4; nj++) {
        int cl = wn + nj * 8 + 2 * tg;
        int c  = col0 + cl;
        float v00 = g_local[r * DD + c]           + gelu_tanh(acc[nj][0]);
        float v01 = g_local[r * DD + c + 1]       + gelu_tanh(acc[nj][1]);
        float v10 = g_local[(r + 8) * DD + c]     + gelu_tanh(acc[nj][2]);
        float v11 = g_local[(r + 8) * DD + c + 1] + gelu_tanh(acc[nj][3]);
        g_local[r * DD + c]           = v00;
        g_local[r * DD + c + 1]       = v01;
        g_local[(r + 8) * DD + c]     = v10;
        g_local[(r + 8) * DD + c + 1] = v11;
#pragma unroll
        for (int o = 0; o < POSW; o++) {
            float w0 = WpS[cl * POSW + o];
            float w1 = WpS[(cl + 1) * POSW + o];
            pp0[o] += v00 * w0 + v01 * w1;
            pp1[o] += v10 * w0 + v11 * w1;
        }
    }

#pragma unroll
    for (int dlt = 1; dlt <= 2; dlt <<= 1)
#pragma unroll
        for (int o = 0; o < POSW; o++) {
            pp0[o] += __shfl_xor_sync(0xFFFFFFFFu, pp0[o], dlt);
            pp1[o] += __shfl_xor_sync(0xFFFFFFFFu, pp1[o], dlt);
        }

    if (tg == 0) {
        int slot = blockIdx.x * 2 + (wn >> 5);
        float* pb = &g_pospart[(size_t)slot * (NN * POSW)];
#pragma unroll
        for (int o = 0; o < POSW; o++) {
            pb[r * POSW + o]       = pp0[o];
            pb[(r + 8) * POSW + o] = pp1[o];
        }
    }
}

// ---------------- kernel: finalize pos + trajectory write --------------
__global__ void __launch_bounds__(256) finalize_pos(float* __restrict__ traj_out) {
    int gidx = blockIdx.x * 256 + threadIdx.x;             // 60 x 256 = 15360
    float acc = 0.0f;
#pragma unroll
    for (int cb = 0; cb < NPART; cb++)
        acc += g_pospart[(size_t)cb * (NN * POSW) + gidx];
    float p = g_pos[gidx] + 0.1f * acc;
    g_pos[gidx] = p;
    traj_out[gidx] = p;
}

// ---------------- launch ----------------
extern "C" void kernel_launch(void* const* d_in, const int* in_sizes, int n_in,
                              void* d_out, int out_size) {
    const float* local    = (const float*)d_in[0];
    const float* pos      = (const float*)d_in[1];
    const float* prev_pos = (const float*)d_in[2];
    const float* disto    = (const float*)d_in[3];
    const float* Wn       = (const float*)d_in[4];
    const float* Wp       = (const float*)d_in[5];
    const int*   resi     = (const int*)d_in[6];
    const int*   chain    = (const int*)d_in[7];
    const int*   batch    = (const int*)d_in[8];
    float* out = (float*)d_out;

    cudaMemcpyToSymbolAsync(g_local, local, (size_t)NN * DD * sizeof(float), 0,
                            cudaMemcpyDeviceToDevice, 0);
    cudaMemcpyToSymbolAsync(g_pos, pos, (size_t)NN * POSW * sizeof(float), 0,
                            cudaMemcpyDeviceToDevice, 0);

    prep_kernel<<<(DD * DD + 255) / 256, 256>>>(Wn);
    based_kernel<<<NN * BSZ / 256, 256>>>(prev_pos, disto, resi, chain, batch);

    uint32_t fk0[NDEPTH], fk1[NDEPTH];
    for (int t = 0; t < NDEPTH; t++)
        tf2x32(0u, 42u, 0u, (uint32_t)t, fk0[t], fk1[t]);

    float* traj_base = out + (size_t)NN * DD + (size_t)NN * POSW;
    dim3 ggrid(DD / 64, NN / 64);

    for (int t = 0; t < NDEPTH; t++) {
        topk_kernel<<<NN, BSZ>>>(fk0[t], fk1[t], batch);
        msg_gemm_tc<<<ggrid, 256>>>();
        gemm_gelu_tc<<<ggrid, 256>>>(Wp);
        finalize_pos<<<NN * POSW / 256, 256>>>(traj_base + (size_t)t * NN * POSW);
    }

    cudaMemcpyFromSymbolAsync(out, g_local, (size_t)NN * DD * sizeof(float), 0,
                              cudaMemcpyDeviceToDevice, 0);
    cudaMemcpyFromSymbolAsync(out + (size_t)NN * DD, g_pos,
                              (size_t)NN * POSW * sizeof(float), 0,
                              cudaMemcpyDeviceToDevice, 0);
}

// round 10
// speedup vs baseline: 1.1745x; 1.0357x over previous
#include <cuda_runtime.h>
#include <cstdint>

// ---------------- problem constants ----------------
#define NN    1024
#define DD    384
#define KK    64
#define POSW  15
#define NBINS 64
#define NDEPTH 4
#define BSZ   256
#define NCB   6            // column blocks (384/64)
#define NPART (NCB * 2)    // pos-partial slots: col-block x warp N-half

// ---------------- persistent device scratch ----------------
__device__ float g_based[NN * BSZ];
__device__ float g_local[NN * DD];              // fp32 master (only copy)
__device__ float g_msgH[NN * DD];               // tf32 hi of msg
__device__ float g_msgL[NN * DD];               // tf32 lo of msg
__device__ float g_WnH[DD * DD];
__device__ float g_WnL[DD * DD];
__device__ float g_pos[NN * POSW];
__device__ float g_pospart[NPART * NN * POSW];

// ---------------- threefry2x32 (bit-exact JAX) ----------------
__host__ __device__ __forceinline__ uint32_t rotl32(uint32_t x, int r) {
    return (x << r) | (x >> (32 - r));
}

__host__ __device__ __forceinline__ void tf2x32(uint32_t k0, uint32_t k1,
                                                uint32_t x0, uint32_t x1,
                                                uint32_t& o0, uint32_t& o1) {
    uint32_t ks2 = k0 ^ k1 ^ 0x1BD11BDAu;
#define TFR(r) { x0 += x1; x1 = rotl32(x1, r); x1 ^= x0; }
    x0 += k0;  x1 += k1;
    TFR(13) TFR(15) TFR(26) TFR(6)
    x0 += k1;  x1 += ks2 + 1u;
    TFR(17) TFR(29) TFR(16) TFR(24)
    x0 += ks2; x1 += k0 + 2u;
    TFR(13) TFR(15) TFR(26) TFR(6)
    x0 += k0;  x1 += k1 + 3u;
    TFR(17) TFR(29) TFR(16) TFR(24)
    x0 += k1;  x1 += ks2 + 4u;
    TFR(13) TFR(15) TFR(26) TFR(6)
    x0 += ks2; x1 += k0 + 5u;
#undef TFR
    o0 = x0; o1 = x1;
}

__device__ __forceinline__ float gumbel_from_bits(uint32_t b) {
    float u = __uint_as_float(0x3F800000u | (b >> 9)) - 1.0f;
    return -logf(-logf(u + 1e-6f) + 1e-6f);
}

__device__ __forceinline__ uint32_t to_tf32(float x) {
    uint32_t r;
    asm("cvt.rna.tf32.f32 %0, %1;" : "=r"(r) : "f"(x));
    return r;
}
__device__ __forceinline__ float to_tf32f(float x) {
    return __uint_as_float(to_tf32(x));
}

__device__ __forceinline__ void mma_tf32(float* c, const uint32_t* a, const uint32_t* b) {
    asm volatile(
        "mma.sync.aligned.m16n8k8.row.col.f32.tf32.tf32.f32 "
        "{%0,%1,%2,%3},{%4,%5,%6,%7},{%8,%9},{%0,%1,%2,%3};"
        : "+f"(c[0]), "+f"(c[1]), "+f"(c[2]), "+f"(c[3])
        : "r"(a[0]), "r"(a[1]), "r"(a[2]), "r"(a[3]), "r"(b[0]), "r"(b[1]));
}

// ---------------- prep: Wn -> tf32 hi/lo (once) -------------------------
__global__ void prep_kernel(const float* __restrict__ Wn) {
    int idx = blockIdx.x * 256 + threadIdx.x;
    if (idx < DD * DD) {
        float v = Wn[idx];
        float h = to_tf32f(v);
        g_WnH[idx] = h;
        g_WnL[idx] = to_tf32f(v - h);
    }
}

// ---------------- kernel: step-invariant base distance ----------------
__global__ void based_kernel(const float* __restrict__ prev_pos,
                             const float* __restrict__ disto,
                             const int* __restrict__ resi,
                             const int* __restrict__ chain,
                             const int* __restrict__ batch) {
    int gid = blockIdx.x * blockDim.x + threadIdx.x;
    if (gid >= NN * BSZ) return;
    int i  = gid >> 8;
    int jj = gid & 255;
    int b  = batch[i];
    int j  = b * BSZ + jj;

    const float4* dp = (const float4*)(disto + ((size_t)i * NN + j) * NBINS);
    float4 v[16];
    float mx = -1e30f;
#pragma unroll
    for (int q = 0; q < 16; q++) {
        v[q] = dp[q];
        mx = fmaxf(mx, fmaxf(fmaxf(v[q].x, v[q].y), fmaxf(v[q].z, v[q].w)));
    }
    const float step = 22.0f / 64.0f;
    float se = 0.0f, swc = 0.0f;
#pragma unroll
    for (int q = 0; q < 16; q++) {
        float e0 = expf(v[q].x - mx), e1 = expf(v[q].y - mx);
        float e2 = expf(v[q].z - mx), e3 = expf(v[q].w - mx);
        se  += e0 + e1 + e2 + e3;
        swc += e0 * (step * (4*q + 0) + 0.5f*step)
             + e1 * (step * (4*q + 1) + 0.5f*step)
             + e2 * (step * (4*q + 2) + 0.5f*step)
             + e3 * (step * (4*q + 3) + 0.5f*step);
    }
    float md = swc / se;

    float d = __int_as_float(0x7f800000);
    if (chain[i] == chain[j]) {
        d = fabsf((float)(resi[i] - resi[j])) * 3.81f;
    }
    if (md < 8.0f) d = fminf(d, md);

    float dx = prev_pos[i * POSW + 3] - prev_pos[j * POSW + 3];
    float dy = prev_pos[i * POSW + 4] - prev_pos[j * POSW + 4];
    float dz = prev_pos[i * POSW + 5] - prev_pos[j * POSW + 5];
    d = fminf(d, sqrtf(dx * dx + dy * dy + dz * dz));

    g_based[gid] = d;
}

// -------- fused top-K (hybrid shfl bitonic) + gather -> msg hi/lo ------
__global__ void __launch_bounds__(384) topk_msg_kernel(uint32_t k0, uint32_t k1,
                                                       const int* __restrict__ batch) {
    int i   = blockIdx.x;
    int tid = threadIdx.x;                                 // 384 threads
    int b   = batch[i];
    bool act = tid < BSZ;                                  // sort uses first 256

    __shared__ unsigned long long s[BSZ];
    __shared__ int sidx[KK];

    unsigned long long K = ~0ull;
    if (act) {
        int jj = tid;
        int j  = b * BSZ + jj;
        float cx = g_pos[i * POSW + 3], cy = g_pos[i * POSW + 4], cz = g_pos[i * POSW + 5];
        float dx = cx - g_pos[j * POSW + 3];
        float dy = cy - g_pos[j * POSW + 4];
        float dz = cz - g_pos[j * POSW + 5];
        float d  = fminf(g_based[i * BSZ + jj], sqrtf(dx * dx + dy * dy + dz * dz));

        uint32_t o0, o1;
        tf2x32(k0, k1, 0u, (uint32_t)(i * NN + j), o0, o1);
        float g = gumbel_from_bits(o0 ^ o1);
        float rd = 3.0f * d - g;

        uint32_t ub = __float_as_uint(rd);
        ub = (ub & 0x80000000u) ? ~ub : (ub | 0x80000000u);
        K = ((unsigned long long)ub << 32) | (unsigned)tid;
    }

    // bitonic sort over first 256 threads: stride<32 via shfl, else smem
    for (unsigned k = 2; k <= BSZ; k <<= 1) {
        bool up = ((tid & k) == 0);
        for (unsigned st = k >> 1; st > 0; st >>= 1) {
            if (st >= 32) {
                if (act) s[tid] = K;
                __syncthreads();
                unsigned long long other = act ? s[tid ^ st] : 0ull;
                __syncthreads();
                if (act) {
                    bool lower = ((tid & st) == 0);
                    bool keepmin = (up == lower);
                    K = keepmin ? (K < other ? K : other) : (K > other ? K : other);
                }
            } else if (act) {                              // warp-uniform guard
                unsigned long long other = __shfl_xor_sync(0xFFFFFFFFu, K, st);
                bool lower = ((tid & st) == 0);
                bool keepmin = (up == lower);
                K = keepmin ? (K < other ? K : other) : (K > other ? K : other);
            }
        }
    }

    if (tid < KK)
        sidx[tid] = b * BSZ + (int)(K & 0xffffffffu);
    __syncthreads();

    // neighbour mean over 64 rows; emit tf32 hi/lo (cnt == 64 always)
    float acc = 0.0f;
#pragma unroll 8
    for (int k = 0; k < KK; k++)
        acc += g_local[sidx[k] * DD + tid];
    float m = acc * (1.0f / 64.0f);
    float h = to_tf32f(m);
    g_msgH[i * DD + tid] = h;
    g_msgL[i * DD + tid] = to_tf32f(m - h);
}

// -------- main GEMM: local += gelu(msg @ Wn), zero-cvt inner loop ------
__device__ __forceinline__ float gelu_tanh(float x) {
    float x3 = x * x * x;
    float t = tanhf(0.7978845608028654f * (x + 0.044715f * x3));
    return 0.5f * x * (1.0f + t);
}

#define GK    16
#define ASTG  20   // A[m][k] stride: 20 ≡ 4 mod 32 -> conflict-free quads
#define BSTN  72   // B[k][n] stride: 72 ≡ 8 mod 32 -> conflict-free
#define NKIT2 (DD / GK)   // 24

__global__ void __launch_bounds__(256) gemm_gelu_tc(const float* __restrict__ Wp) {
    __shared__ float AsH[2][64 * ASTG];
    __shared__ float AsL[2][64 * ASTG];
    __shared__ float BsH[2][GK * BSTN];
    __shared__ float BsL[2][GK * BSTN];
    __shared__ float WpS[64 * POSW];

    int tid  = threadIdx.x;
    int warp = tid >> 5, lane = tid & 31;
    int wm = (warp & 3) * 16;
    int wn = (warp >> 2) * 32;
    int row0 = blockIdx.y * 64;
    int col0 = blockIdx.x * 64;
    int g  = lane >> 2;
    int tg = lane & 3;

    float acc[4][4] = {};

    int am = tid >> 2;            // 0..63
    int ak = (tid & 3) * 4;       // 0,4,8,12
    int bk = tid >> 4;            // 0..15
    int bn = (tid & 15) * 4;      // 0..60

    uint32_t sah[2], sal[2], sbh[2], sbl[2];
    sah[0] = (uint32_t)__cvta_generic_to_shared(&AsH[0][am * ASTG + ak]);
    sah[1] = (uint32_t)__cvta_generic_to_shared(&AsH[1][am * ASTG + ak]);
    sal[0] = (uint32_t)__cvta_generic_to_shared(&AsL[0][am * ASTG + ak]);
    sal[1] = (uint32_t)__cvta_generic_to_shared(&AsL[1][am * ASTG + ak]);
    sbh[0] = (uint32_t)__cvta_generic_to_shared(&BsH[0][bk * BSTN + bn]);
    sbh[1] = (uint32_t)__cvta_generic_to_shared(&BsH[1][bk * BSTN + bn]);
    sbl[0] = (uint32_t)__cvta_generic_to_shared(&BsL[0][bk * BSTN + bn]);
    sbl[1] = (uint32_t)__cvta_generic_to_shared(&BsL[1][bk * BSTN + bn]);

#define GSTAGE(it, buf)                                                          \
    {                                                                            \
        int k0 = (it) * GK;                                                      \
        const float* pah = &g_msgH[(row0 + am) * DD + k0 + ak];                  \
        asm volatile("cp.async.cg.shared.global [%0],[%1],16;" :: "r"(sah[buf]), "l"(pah)); \
        const float* pal = &g_msgL[(row0 + am) * DD + k0 + ak];                  \
        asm volatile("cp.async.cg.shared.global [%0],[%1],16;" :: "r"(sal[buf]), "l"(pal)); \
        const float* pbh = &g_WnH[(size_t)(k0 + bk) * DD + col0 + bn];           \
        asm volatile("cp.async.cg.shared.global [%0],[%1],16;" :: "r"(sbh[buf]), "l"(pbh)); \
        const float* pbl = &g_WnL[(size_t)(k0 + bk) * DD + col0 + bn];           \
        asm volatile("cp.async.cg.shared.global [%0],[%1],16;" :: "r"(sbl[buf]), "l"(pbl)); \
        asm volatile("cp.async.commit_group;");                                  \
    }

    GSTAGE(0, 0)

    for (int idx = tid; idx < 64 * POSW; idx += 256)
        WpS[idx] = Wp[col0 * POSW + idx];

    for (int it = 0; it < NKIT2; ++it) {
        int cur = it & 1;
        if (it + 1 < NKIT2) {
            GSTAGE(it + 1, !cur)
            asm volatile("cp.async.wait_group 1;");
        } else {
            asm volatile("cp.async.wait_group 0;");
        }
        __syncthreads();

        const float* AH = AsH[cur];
        const float* AL = AsL[cur];
        const float* BH = BsH[cur];
        const float* BL = BsL[cur];
#pragma unroll
        for (int ks = 0; ks < GK; ks += 8) {
            uint32_t ah[4] = {
                __float_as_uint(AH[(wm + g) * ASTG + ks + tg]),
                __float_as_uint(AH[(wm + g + 8) * ASTG + ks + tg]),
                __float_as_uint(AH[(wm + g) * ASTG + ks + tg + 4]),
                __float_as_uint(AH[(wm + g + 8) * ASTG + ks + tg + 4]) };
            uint32_t al[4] = {
                __float_as_uint(AL[(wm + g) * ASTG + ks + tg]),
                __float_as_uint(AL[(wm + g + 8) * ASTG + ks + tg]),
                __float_as_uint(AL[(wm + g) * ASTG + ks + tg + 4]),
                __float_as_uint(AL[(wm + g + 8) * ASTG + ks + tg + 4]) };
#pragma unroll
            for (int nj = 0; nj < 4; nj++) {
                int cc = wn + nj * 8 + g;
                uint32_t bh[2] = { __float_as_uint(BH[(ks + tg) * BSTN + cc]),
                                   __float_as_uint(BH[(ks + tg + 4) * BSTN + cc]) };
                uint32_t bl[2] = { __float_as_uint(BL[(ks + tg) * BSTN + cc]),
                                   __float_as_uint(BL[(ks + tg + 4) * BSTN + cc]) };
                mma_tf32(acc[nj], al, bh);
                mma_tf32(acc[nj], ah, bl);
                mma_tf32(acc[nj], ah, bh);
            }
        }
        __syncthreads();
    }

    // epilogue: local += gelu(acc); pos partials
    int r = row0 + wm + g;
    float pp0[POSW], pp1[POSW];
#pragma unroll
    for (int o = 0; o < POSW; o++) { pp0[o] = 0.0f; pp1[o] = 0.0f; }

#pragma unroll
    for (int nj = 0; nj < 4; nj++) {
        int cl = wn + nj * 8 + 2 * tg;
        int c  = col0 + cl;
        float v00 = g_local[r * DD + c]           + gelu_tanh(acc[nj][0]);
        float v01 = g_local[r * DD + c + 1]       + gelu_tanh(acc[nj][1]);
        float v10 = g_local[(r + 8) * DD + c]     + gelu_tanh(acc[nj][2]);
        float v11 = g_local[(r + 8) * DD + c + 1] + gelu_tanh(acc[nj][3]);
        g_local[r * DD + c]           = v00;
        g_local[r * DD + c + 1]       = v01;
        g_local[(r + 8) * DD + c]     = v10;
        g_local[(r + 8) * DD + c + 1] = v11;
#pragma unroll
        for (int o = 0; o < POSW; o++) {
            float w0 = WpS[cl * POSW + o];
            float w1 = WpS[(cl + 1) * POSW + o];
            pp0[o] += v00 * w0 + v01 * w1;
            pp1[o] += v10 * w0 + v11 * w1;
        }
    }

#pragma unroll
    for (int dlt = 1; dlt <= 2; dlt <<= 1)
#pragma unroll
        for (int o = 0; o < POSW; o++) {
            pp0[o] += __shfl_xor_sync(0xFFFFFFFFu, pp0[o], dlt);
            pp1[o] += __shfl_xor_sync(0xFFFFFFFFu, pp1[o], dlt);
        }

    if (tg == 0) {
        int slot = blockIdx.x * 2 + (wn >> 5);
        float* pb = &g_pospart[(size_t)slot * (NN * POSW)];
#pragma unroll
        for (int o = 0; o < POSW; o++) {
            pb[r * POSW + o]       = pp0[o];
            pb[(r + 8) * POSW + o] = pp1[o];
        }
    }
}

// ---------------- kernel: finalize pos + trajectory write --------------
__global__ void __launch_bounds__(256) finalize_pos(float* __restrict__ traj_out) {
    int gidx = blockIdx.x * 256 + threadIdx.x;             // 60 x 256 = 15360
    float acc = 0.0f;
#pragma unroll
    for (int cb = 0; cb < NPART; cb++)
        acc += g_pospart[(size_t)cb * (NN * POSW) + gidx];
    float p = g_pos[gidx] + 0.1f * acc;
    g_pos[gidx] = p;
    traj_out[gidx] = p;
}

// ---------------- launch ----------------
extern "C" void kernel_launch(void* const* d_in, const int* in_sizes, int n_in,
                              void* d_out, int out_size) {
    const float* local    = (const float*)d_in[0];
    const float* pos      = (const float*)d_in[1];
    const float* prev_pos = (const float*)d_in[2];
    const float* disto    = (const float*)d_in[3];
    const float* Wn       = (const float*)d_in[4];
    const float* Wp       = (const float*)d_in[5];
    const int*   resi     = (const int*)d_in[6];
    const int*   chain    = (const int*)d_in[7];
    const int*   batch    = (const int*)d_in[8];
    float* out = (float*)d_out;

    cudaMemcpyToSymbolAsync(g_local, local, (size_t)NN * DD * sizeof(float), 0,
                            cudaMemcpyDeviceToDevice, 0);
    cudaMemcpyToSymbolAsync(g_pos, pos, (size_t)NN * POSW * sizeof(float), 0,
                            cudaMemcpyDeviceToDevice, 0);

    prep_kernel<<<(DD * DD + 255) / 256, 256>>>(Wn);
    based_kernel<<<NN * BSZ / 256, 256>>>(prev_pos, disto, resi, chain, batch);

    uint32_t fk0[NDEPTH], fk1[NDEPTH];
    for (int t = 0; t < NDEPTH; t++)
        tf2x32(0u, 42u, 0u, (uint32_t)t, fk0[t], fk1[t]);

    float* traj_base = out + (size_t)NN * DD + (size_t)NN * POSW;
    dim3 ggrid(DD / 64, NN / 64);

    for (int t = 0; t < NDEPTH; t++) {
        topk_msg_kernel<<<NN, 384>>>(fk0[t], fk1[t], batch);
        gemm_gelu_tc<<<ggrid, 256>>>(Wp);
        finalize_pos<<<NN * POSW / 256, 256>>>(traj_base + (size_t)t * NN * POSW);
    }

    cudaMemcpyFromSymbolAsync(out, g_local, (size_t)NN * DD * sizeof(float), 0,
                              cudaMemcpyDeviceToDevice, 0);
    cudaMemcpyFromSymbolAsync(out + (size_t)NN * DD, g_pos,
                              (size_t)NN * POSW * sizeof(float), 0,
                              cudaMemcpyDeviceToDevice, 0);
}

// round 11
// speedup vs baseline: 1.1883x; 1.0118x over previous
#include <cuda_runtime.h>
#include <cstdint>

// ---------------- problem constants ----------------
#define NN    1024
#define DD    384
#define KK    64
#define POSW  15
#define NBINS 64
#define NDEPTH 4
#define BSZ   256
#define NCB   6            // column blocks (384/64)
#define NPART (NCB * 2)    // pos-partial slots: col-block x warp N-half

// ---------------- persistent device scratch ----------------
__device__ float g_based[NN * BSZ];
__device__ float g_local[NN * DD];              // fp32 master (only copy)
__device__ float g_msgH[NN * DD];               // tf32 hi of msg
__device__ float g_msgL[NN * DD];               // tf32 lo of msg
__device__ float g_WnH[DD * DD];
__device__ float g_WnL[DD * DD];
__device__ float g_pos[NN * POSW];
__device__ float g_pospart[NPART * NN * POSW];

// ---------------- threefry2x32 (bit-exact JAX) ----------------
__host__ __device__ __forceinline__ uint32_t rotl32(uint32_t x, int r) {
    return (x << r) | (x >> (32 - r));
}

__host__ __device__ __forceinline__ void tf2x32(uint32_t k0, uint32_t k1,
                                                uint32_t x0, uint32_t x1,
                                                uint32_t& o0, uint32_t& o1) {
    uint32_t ks2 = k0 ^ k1 ^ 0x1BD11BDAu;
#define TFR(r) { x0 += x1; x1 = rotl32(x1, r); x1 ^= x0; }
    x0 += k0;  x1 += k1;
    TFR(13) TFR(15) TFR(26) TFR(6)
    x0 += k1;  x1 += ks2 + 1u;
    TFR(17) TFR(29) TFR(16) TFR(24)
    x0 += ks2; x1 += k0 + 2u;
    TFR(13) TFR(15) TFR(26) TFR(6)
    x0 += k0;  x1 += k1 + 3u;
    TFR(17) TFR(29) TFR(16) TFR(24)
    x0 += k1;  x1 += ks2 + 4u;
    TFR(13) TFR(15) TFR(26) TFR(6)
    x0 += ks2; x1 += k0 + 5u;
#undef TFR
    o0 = x0; o1 = x1;
}

__device__ __forceinline__ float gumbel_from_bits(uint32_t b) {
    float u = __uint_as_float(0x3F800000u | (b >> 9)) - 1.0f;
    return -logf(-logf(u + 1e-6f) + 1e-6f);
}

__device__ __forceinline__ uint32_t to_tf32(float x) {
    uint32_t r;
    asm("cvt.rna.tf32.f32 %0, %1;" : "=r"(r) : "f"(x));
    return r;
}
__device__ __forceinline__ float to_tf32f(float x) {
    return __uint_as_float(to_tf32(x));
}

__device__ __forceinline__ void mma_tf32(float* c, const uint32_t* a, const uint32_t* b) {
    asm volatile(
        "mma.sync.aligned.m16n8k8.row.col.f32.tf32.tf32.f32 "
        "{%0,%1,%2,%3},{%4,%5,%6,%7},{%8,%9},{%0,%1,%2,%3};"
        : "+f"(c[0]), "+f"(c[1]), "+f"(c[2]), "+f"(c[3])
        : "r"(a[0]), "r"(a[1]), "r"(a[2]), "r"(a[3]), "r"(b[0]), "r"(b[1]));
}

// ---------------- prep: Wn -> tf32 hi/lo (once) -------------------------
__global__ void prep_kernel(const float* __restrict__ Wn) {
    int idx = blockIdx.x * 256 + threadIdx.x;
    if (idx < DD * DD) {
        float v = Wn[idx];
        float h = to_tf32f(v);
        g_WnH[idx] = h;
        g_WnL[idx] = to_tf32f(v - h);
    }
}

// ---------------- kernel: step-invariant base distance ----------------
__global__ void based_kernel(const float* __restrict__ prev_pos,
                             const float* __restrict__ disto,
                             const int* __restrict__ resi,
                             const int* __restrict__ chain,
                             const int* __restrict__ batch) {
    int gid = blockIdx.x * blockDim.x + threadIdx.x;
    if (gid >= NN * BSZ) return;
    int i  = gid >> 8;
    int jj = gid & 255;
    int b  = batch[i];
    int j  = b * BSZ + jj;

    const float4* dp = (const float4*)(disto + ((size_t)i * NN + j) * NBINS);
    float4 v[16];
    float mx = -1e30f;
#pragma unroll
    for (int q = 0; q < 16; q++) {
        v[q] = dp[q];
        mx = fmaxf(mx, fmaxf(fmaxf(v[q].x, v[q].y), fmaxf(v[q].z, v[q].w)));
    }
    const float step = 22.0f / 64.0f;
    float se = 0.0f, swc = 0.0f;
#pragma unroll
    for (int q = 0; q < 16; q++) {
        float e0 = expf(v[q].x - mx), e1 = expf(v[q].y - mx);
        float e2 = expf(v[q].z - mx), e3 = expf(v[q].w - mx);
        se  += e0 + e1 + e2 + e3;
        swc += e0 * (step * (4*q + 0) + 0.5f*step)
             + e1 * (step * (4*q + 1) + 0.5f*step)
             + e2 * (step * (4*q + 2) + 0.5f*step)
             + e3 * (step * (4*q + 3) + 0.5f*step);
    }
    float md = swc / se;

    float d = __int_as_float(0x7f800000);
    if (chain[i] == chain[j]) {
        d = fabsf((float)(resi[i] - resi[j])) * 3.81f;
    }
    if (md < 8.0f) d = fminf(d, md);

    float dx = prev_pos[i * POSW + 3] - prev_pos[j * POSW + 3];
    float dy = prev_pos[i * POSW + 4] - prev_pos[j * POSW + 4];
    float dz = prev_pos[i * POSW + 5] - prev_pos[j * POSW + 5];
    d = fminf(d, sqrtf(dx * dx + dy * dy + dz * dz));

    g_based[gid] = d;
}

// -------- fused top-K (hybrid shfl bitonic) + gather -> msg hi/lo ------
__global__ void __launch_bounds__(384) topk_msg_kernel(uint32_t k0, uint32_t k1,
                                                       const int* __restrict__ batch) {
    int i   = blockIdx.x;
    int tid = threadIdx.x;                                 // 384 threads
    int b   = batch[i];
    bool act = tid < BSZ;                                  // sort uses first 256

    __shared__ unsigned long long s[BSZ];
    __shared__ int sidx[KK];

    unsigned long long K = ~0ull;
    if (act) {
        int jj = tid;
        int j  = b * BSZ + jj;
        float cx = g_pos[i * POSW + 3], cy = g_pos[i * POSW + 4], cz = g_pos[i * POSW + 5];
        float dx = cx - g_pos[j * POSW + 3];
        float dy = cy - g_pos[j * POSW + 4];
        float dz = cz - g_pos[j * POSW + 5];
        float d  = fminf(g_based[i * BSZ + jj], sqrtf(dx * dx + dy * dy + dz * dz));

        uint32_t o0, o1;
        tf2x32(k0, k1, 0u, (uint32_t)(i * NN + j), o0, o1);
        float g = gumbel_from_bits(o0 ^ o1);
        float rd = 3.0f * d - g;

        uint32_t ub = __float_as_uint(rd);
        ub = (ub & 0x80000000u) ? ~ub : (ub | 0x80000000u);
        K = ((unsigned long long)ub << 32) | (unsigned)tid;
    }

    for (unsigned k = 2; k <= BSZ; k <<= 1) {
        bool up = ((tid & k) == 0);
        for (unsigned st = k >> 1; st > 0; st >>= 1) {
            if (st >= 32) {
                if (act) s[tid] = K;
                __syncthreads();
                unsigned long long other = act ? s[tid ^ st] : 0ull;
                __syncthreads();
                if (act) {
                    bool lower = ((tid & st) == 0);
                    bool keepmin = (up == lower);
                    K = keepmin ? (K < other ? K : other) : (K > other ? K : other);
                }
            } else if (act) {
                unsigned long long other = __shfl_xor_sync(0xFFFFFFFFu, K, st);
                bool lower = ((tid & st) == 0);
                bool keepmin = (up == lower);
                K = keepmin ? (K < other ? K : other) : (K > other ? K : other);
            }
        }
    }

    if (tid < KK)
        sidx[tid] = b * BSZ + (int)(K & 0xffffffffu);
    __syncthreads();

    float acc = 0.0f;
#pragma unroll 8
    for (int k = 0; k < KK; k++)
        acc += g_local[sidx[k] * DD + tid];
    float m = acc * (1.0f / 64.0f);
    float h = to_tf32f(m);
    g_msgH[i * DD + tid] = h;
    g_msgL[i * DD + tid] = to_tf32f(m - h);
}

// -------- main GEMM: local += gelu(msg @ Wn), zero-cvt, GBK=32 ---------
__device__ __forceinline__ float gelu_tanh(float x) {
    float x3 = x * x * x;
    float t = tanhf(0.7978845608028654f * (x + 0.044715f * x3));
    return 0.5f * x * (1.0f + t);
}

#define GBK   32
#define AST   36   // A[m][k] stride: 36 ≡ 4 mod 32 -> conflict-free
#define BSTN  72   // B[k][n] stride: 72 ≡ 8 mod 32 -> conflict-free
#define NKIT  (DD / GBK)   // 12

// dynamic smem layout (floats)
#define OFF_AH 0
#define OFF_AL (OFF_AH + 2 * 64 * AST)     // 4608
#define OFF_BH (OFF_AL + 2 * 64 * AST)     // 9216
#define OFF_BL (OFF_BH + 2 * GBK * BSTN)   // 13824
#define OFF_WP (OFF_BL + 2 * GBK * BSTN)   // 18432
#define SMEM_FLOATS (OFF_WP + 64 * POSW)   // 19392 -> 77568 B

__global__ void __launch_bounds__(256) gemm_gelu_tc(const float* __restrict__ Wp) {
    extern __shared__ float dsm[];
    float* AsH = dsm + OFF_AH;
    float* AsL = dsm + OFF_AL;
    float* BsH = dsm + OFF_BH;
    float* BsL = dsm + OFF_BL;
    float* WpS = dsm + OFF_WP;

    int tid  = threadIdx.x;
    int warp = tid >> 5, lane = tid & 31;
    int wm = (warp & 3) * 16;
    int wn = (warp >> 2) * 32;
    int row0 = blockIdx.y * 64;
    int col0 = blockIdx.x * 64;
    int g  = lane >> 2;
    int tg = lane & 3;

    float acc[4][4] = {};

    int am = tid >> 2;            // 0..63
    int ak = (tid & 3) * 8;       // 0,8,16,24
    int bk = tid >> 3;            // 0..31
    int bn = (tid & 7) * 8;       // 0..56

    uint32_t sah[2], sal[2], sbh[2], sbl[2];
#pragma unroll
    for (int u = 0; u < 2; u++) {
        sah[u] = (uint32_t)__cvta_generic_to_shared(&AsH[u * 64 * AST + am * AST + ak]);
        sal[u] = (uint32_t)__cvta_generic_to_shared(&AsL[u * 64 * AST + am * AST + ak]);
        sbh[u] = (uint32_t)__cvta_generic_to_shared(&BsH[u * GBK * BSTN + bk * BSTN + bn]);
        sbl[u] = (uint32_t)__cvta_generic_to_shared(&BsL[u * GBK * BSTN + bk * BSTN + bn]);
    }

#define GSTAGE(it, buf)                                                          \
    {                                                                            \
        int k0 = (it) * GBK;                                                     \
        const float* pah = &g_msgH[(row0 + am) * DD + k0 + ak];                  \
        asm volatile("cp.async.cg.shared.global [%0],[%1],16;" :: "r"(sah[buf]), "l"(pah)); \
        asm volatile("cp.async.cg.shared.global [%0],[%1],16;" :: "r"(sah[buf] + 16), "l"(pah + 4)); \
        const float* pal = &g_msgL[(row0 + am) * DD + k0 + ak];                  \
        asm volatile("cp.async.cg.shared.global [%0],[%1],16;" :: "r"(sal[buf]), "l"(pal)); \
        asm volatile("cp.async.cg.shared.global [%0],[%1],16;" :: "r"(sal[buf] + 16), "l"(pal + 4)); \
        const float* pbh = &g_WnH[(size_t)(k0 + bk) * DD + col0 + bn];           \
        asm volatile("cp.async.cg.shared.global [%0],[%1],16;" :: "r"(sbh[buf]), "l"(pbh)); \
        asm volatile("cp.async.cg.shared.global [%0],[%1],16;" :: "r"(sbh[buf] + 16), "l"(pbh + 4)); \
        const float* pbl = &g_WnL[(size_t)(k0 + bk) * DD + col0 + bn];           \
        asm volatile("cp.async.cg.shared.global [%0],[%1],16;" :: "r"(sbl[buf]), "l"(pbl)); \
        asm volatile("cp.async.cg.shared.global [%0],[%1],16;" :: "r"(sbl[buf] + 16), "l"(pbl + 4)); \
        asm volatile("cp.async.commit_group;");                                  \
    }

    GSTAGE(0, 0)

    for (int idx = tid; idx < 64 * POSW; idx += 256)
        WpS[idx] = Wp[col0 * POSW + idx];

    for (int it = 0; it < NKIT; ++it) {
        int cur = it & 1;
        if (it + 1 < NKIT) {
            GSTAGE(it + 1, !cur)
            asm volatile("cp.async.wait_group 1;");
        } else {
            asm volatile("cp.async.wait_group 0;");
        }
        __syncthreads();

        const float* AH = AsH + cur * 64 * AST;
        const float* AL = AsL + cur * 64 * AST;
        const float* BH = BsH + cur * GBK * BSTN;
        const float* BL = BsL + cur * GBK * BSTN;
#pragma unroll
        for (int ks = 0; ks < GBK; ks += 8) {
            uint32_t ah[4] = {
                __float_as_uint(AH[(wm + g) * AST + ks + tg]),
                __float_as_uint(AH[(wm + g + 8) * AST + ks + tg]),
                __float_as_uint(AH[(wm + g) * AST + ks + tg + 4]),
                __float_as_uint(AH[(wm + g + 8) * AST + ks + tg + 4]) };
            uint32_t al[4] = {
                __float_as_uint(AL[(wm + g) * AST + ks + tg]),
                __float_as_uint(AL[(wm + g + 8) * AST + ks + tg]),
                __float_as_uint(AL[(wm + g) * AST + ks + tg + 4]),
                __float_as_uint(AL[(wm + g + 8) * AST + ks + tg + 4]) };
#pragma unroll
            for (int nj = 0; nj < 4; nj++) {
                int cc = wn + nj * 8 + g;
                uint32_t bh[2] = { __float_as_uint(BH[(ks + tg) * BSTN + cc]),
                                   __float_as_uint(BH[(ks + tg + 4) * BSTN + cc]) };
                uint32_t bl[2] = { __float_as_uint(BL[(ks + tg) * BSTN + cc]),
                                   __float_as_uint(BL[(ks + tg + 4) * BSTN + cc]) };
                mma_tf32(acc[nj], al, bh);
                mma_tf32(acc[nj], ah, bl);
                mma_tf32(acc[nj], ah, bh);
            }
        }
        __syncthreads();
    }

    // epilogue: local += gelu(acc); pos partials
    int r = row0 + wm + g;
    float pp0[POSW], pp1[POSW];
#pragma unroll
    for (int o = 0; o < POSW; o++) { pp0[o] = 0.0f; pp1[o] = 0.0f; }

#pragma unroll
    for (int nj = 0; nj < 4; nj++) {
        int cl = wn + nj * 8 + 2 * tg;
        int c  = col0 + cl;
        float v00 = g_local[r * DD + c]           + gelu_tanh(acc[nj][0]);
        float v01 = g_local[r * DD + c + 1]       + gelu_tanh(acc[nj][1]);
        float v10 = g_local[(r + 8) * DD + c]     + gelu_tanh(acc[nj][2]);
        float v11 = g_local[(r + 8) * DD + c + 1] + gelu_tanh(acc[nj][3]);
        g_local[r * DD + c]           = v00;
        g_local[r * DD + c + 1]       = v01;
        g_local[(r + 8) * DD + c]     = v10;
        g_local[(r + 8) * DD + c + 1] = v11;
#pragma unroll
        for (int o = 0; o < POSW; o++) {
            float w0 = WpS[cl * POSW + o];
            float w1 = WpS[(cl + 1) * POSW + o];
            pp0[o] += v00 * w0 + v01 * w1;
            pp1[o] += v10 * w0 + v11 * w1;
        }
    }

#pragma unroll
    for (int dlt = 1; dlt <= 2; dlt <<= 1)
#pragma unroll
        for (int o = 0; o < POSW; o++) {
            pp0[o] += __shfl_xor_sync(0xFFFFFFFFu, pp0[o], dlt);
            pp1[o] += __shfl_xor_sync(0xFFFFFFFFu, pp1[o], dlt);
        }

    if (tg == 0) {
        int slot = blockIdx.x * 2 + (wn >> 5);
        float* pb = &g_pospart[(size_t)slot * (NN * POSW)];
#pragma unroll
        for (int o = 0; o < POSW; o++) {
            pb[r * POSW + o]       = pp0[o];
            pb[(r + 8) * POSW + o] = pp1[o];
        }
    }
}

// ---------------- kernel: finalize pos + trajectory write --------------
__global__ void __launch_bounds__(256) finalize_pos(float* __restrict__ traj_out) {
    int gidx = blockIdx.x * 256 + threadIdx.x;             // 60 x 256 = 15360
    float acc = 0.0f;
#pragma unroll
    for (int cb = 0; cb < NPART; cb++)
        acc += g_pospart[(size_t)cb * (NN * POSW) + gidx];
    float p = g_pos[gidx] + 0.1f * acc;
    g_pos[gidx] = p;
    traj_out[gidx] = p;
}

// ---------------- launch ----------------
extern "C" void kernel_launch(void* const* d_in, const int* in_sizes, int n_in,
                              void* d_out, int out_size) {
    const float* local    = (const float*)d_in[0];
    const float* pos      = (const float*)d_in[1];
    const float* prev_pos = (const float*)d_in[2];
    const float* disto    = (const float*)d_in[3];
    const float* Wn       = (const float*)d_in[4];
    const float* Wp       = (const float*)d_in[5];
    const int*   resi     = (const int*)d_in[6];
    const int*   chain    = (const int*)d_in[7];
    const int*   batch    = (const int*)d_in[8];
    float* out = (float*)d_out;

    static bool attr_set = false;
    if (!attr_set) {
        cudaFuncSetAttribute(gemm_gelu_tc,
                             cudaFuncAttributeMaxDynamicSharedMemorySize,
                             SMEM_FLOATS * sizeof(float));
        attr_set = true;
    }

    cudaMemcpyToSymbolAsync(g_local, local, (size_t)NN * DD * sizeof(float), 0,
                            cudaMemcpyDeviceToDevice, 0);
    cudaMemcpyToSymbolAsync(g_pos, pos, (size_t)NN * POSW * sizeof(float), 0,
                            cudaMemcpyDeviceToDevice, 0);

    prep_kernel<<<(DD * DD + 255) / 256, 256>>>(Wn);
    based_kernel<<<NN * BSZ / 256, 256>>>(prev_pos, disto, resi, chain, batch);

    uint32_t fk0[NDEPTH], fk1[NDEPTH];
    for (int t = 0; t < NDEPTH; t++)
        tf2x32(0u, 42u, 0u, (uint32_t)t, fk0[t], fk1[t]);

    float* traj_base = out + (size_t)NN * DD + (size_t)NN * POSW;
    dim3 ggrid(DD / 64, NN / 64);

    for (int t = 0; t < NDEPTH; t++) {
        topk_msg_kernel<<<NN, 384>>>(fk0[t], fk1[t], batch);
        gemm_gelu_tc<<<ggrid, 256, SMEM_FLOATS * sizeof(float)>>>(Wp);
        finalize_pos<<<NN * POSW / 256, 256>>>(traj_base + (size_t)t * NN * POSW);
    }

    cudaMemcpyFromSymbolAsync(out, g_local, (size_t)NN * DD * sizeof(float), 0,
                              cudaMemcpyDeviceToDevice, 0);
    cudaMemcpyFromSymbolAsync(out + (size_t)NN * DD, g_pos,
                              (size_t)NN * POSW * sizeof(float), 0,
                              cudaMemcpyDeviceToDevice, 0);
}